// round 3
// baseline (speedup 1.0000x reference)
#include <cuda_runtime.h>
#include <math.h>

#define NB   4
#define CIN  192
#define HH   128
#define WW   128
#define PP   (HH*WW)       // 16384
#define C1c  48
#define C0c  16
#define CMc  16
#define BATCH 64           // NB * CMc
#define JW   65
#define P65  (128*JW)      // 8320

// ---------------- device scratch (no allocation allowed) ----------------
static __device__ double2 g_chrp1[255];
static __device__ double2 g_chrp2[128];
static __device__ double2 g_E[509];
static __device__ double  g_S[509];

static __device__ float2  g_M   [128*128];
static __device__ float2  g_Cm  [128*128];
static __device__ float2  g_Minv[128*128];
static __device__ float2  g_Fh  [128*128];
static __device__ float2  g_Fhi [128*128];
static __device__ float2  g_Fw  [JW*128];
static __device__ float2  g_Bw  [JW*128];

static __device__ float   g_x1 [NB*C1c*PP];
static __device__ float2  g_T  [BATCH*128*128];
static __device__ float2  g_F  [BATCH*128*128];
static __device__ float   g_mag[BATCH*PP];
static __device__ float   g_pha[BATCH*PP];
static __device__ float   g_mm2[BATCH*PP];
static __device__ float   g_cA [BATCH*PP];
static __device__ float   g_cB [BATCH*PP];
static __device__ float   g_cS [BATCH*PP];
static __device__ float   g_magout[BATCH*PP];
static __device__ float   g_phaout[BATCH*PP];
static __device__ float2  g_T65[BATCH*P65];
static __device__ float2  g_F65[BATCH*P65];
static __device__ float   g_fm[BATCH*P65];
static __device__ float   g_fp[BATCH*P65];
static __device__ float   g_mo[BATCH*P65];
static __device__ float   g_po[BATCH*P65];
static __device__ float   g_cat[NB*C1c*PP];

// ---------------- matrix construction ----------------
__global__ void k_tables() {
    int t = threadIdx.x;
    const double PI = 3.14159265358979323846;
    double tana2 = tan(PI / 8.0);     // tan(alpha/2), alpha = pi/4
    double sina  = sin(PI / 4.0);
    double coef  = tana2 / 512.0;     // chirp: exp(-i*pi*coef*n^2)
    double ec    = 1.0 / (512.0 * sina); // E: exp(+i*pi*ec*d^2)
    for (int j = t; j < 255; j += 512) {
        double n = (double)(j - 127);
        double s, c; sincospi(-coef * n * n, &s, &c);
        g_chrp1[j] = make_double2(c, s);
    }
    for (int r = t; r < 128; r += 512) {
        double n = 2.0 * r - 127.0;
        double s, c; sincospi(-coef * n * n, &s, &c);
        g_chrp2[r] = make_double2(c, s);
    }
    for (int i = t; i < 509; i += 512) {
        double d = (double)(i - 254);
        double s, c; sincospi(ec * d * d, &s, &c);
        g_E[i] = make_double2(c, s);
        int m = i - 254;
        double sv;
        if (m == 0) sv = 1.0;
        else if ((m & 1) == 0) sv = 0.0;
        else {
            double x = 0.5 * (double)m;
            sv = sinpi(x) / (3.14159265358979323846 * x);
        }
        g_S[i] = sv;
    }
}

__global__ void k_dft() {
    int idx = blockIdx.x * 256 + threadIdx.x;
    if (idx < 128 * 128) {
        int u = idx >> 7, v = idx & 127;
        int e1 = ((u + 64) * (v + 64)) & 127;
        double s, c; sincospi(2.0 * e1 / 128.0, &s, &c);
        double inv = 1.0 / sqrt(128.0);
        g_Cm[idx] = make_float2((float)(c * inv), (float)(s * inv));
        int e2 = (u * v) & 127;
        double s2, c2; sincospi(-2.0 * e2 / 128.0, &s2, &c2);
        g_Fh[idx] = make_float2((float)c2, (float)s2);
        double s3, c3; sincospi(2.0 * e2 / 128.0, &s3, &c3);
        g_Fhi[idx] = make_float2((float)(c3 / 128.0), (float)(s3 / 128.0));
    }
    if (idx < JW * 128) {
        int k = idx / 128, w = idx & 127;
        int e = (k * w) & 127;
        double s, c; sincospi(-2.0 * e / 128.0, &s, &c);
        g_Fw[idx] = make_float2((float)c, (float)s);
        float2 bw;
        if (k == 0)       bw = make_float2(1.0f / 128.0f, 0.f);
        else if (k == 64) bw = make_float2(((w & 1) ? -1.0f : 1.0f) / 128.0f, 0.f);
        else {
            double s4, c4; sincospi(2.0 * e / 128.0, &s4, &c4);
            bw = make_float2((float)(c4 * 2.0 / 128.0), (float)(s4 * 2.0 / 128.0));
        }
        g_Bw[idx] = bw;
    }
}

__global__ void k_buildM() {
    int idx = blockIdx.x * 256 + threadIdx.x;
    if (idx >= 128 * 128) return;
    int r = idx >> 7, k = idx & 127;
    double ax = 0.0, ay = 0.0;
    for (int j = 0; j < 255; j++) {
        double s = g_S[j - 2 * k + 254];
        if (s != 0.0) {
            double2 c1 = g_chrp1[j];
            double2 e  = g_E[2 * r - j + 254];
            ax += (c1.x * e.x - c1.y * e.y) * s;
            ay += (c1.x * e.y + c1.y * e.x) * s;
        }
    }
    const double PI = 3.14159265358979323846;
    double sina = sin(PI / 4.0);
    double amp  = sqrt(1.0 / (512.0 * sina));   // sqrt(c/pi)
    double ps, pc; sincospi(-0.125, &ps, &pc);  // exp(-i pi/8)
    double2 c2 = g_chrp2[r];
    double fr = amp * (pc * c2.x - ps * c2.y);
    double fi = amp * (pc * c2.y + ps * c2.x);
    g_M[idx] = make_float2((float)(fr * ax - fi * ay),
                           (float)(fr * ay + fi * ax));
}

__global__ void k_buildMinv() {
    int idx = blockIdx.x * 256 + threadIdx.x;
    if (idx >= 128 * 128) return;
    int r = idx >> 7, v = idx & 127;
    double ax = 0.0, ay = 0.0;
    for (int u = 0; u < 128; u++) {
        float2 a = g_M[r * 128 + u];
        float2 b = g_Cm[u * 128 + v];
        ax += (double)a.x * b.x - (double)a.y * b.y;
        ay += (double)a.x * b.y + (double)a.y * b.x;
    }
    g_Minv[idx] = make_float2((float)ax, (float)ay);
}

// ---------------- generic 1x1 conv (GEMM) ----------------
// Y[n][ob+o][p] = sum_c W[ob+o][c] * X[n][c][p] (+bias)
__global__ void __launch_bounds__(128)
k_g1x1(const float* __restrict__ X, const float* __restrict__ Wt,
       const float* __restrict__ Bs, float* __restrict__ Y,
       int Cc, int P, int xStrideN, int yStrideN) {
    __shared__ float sW[16 * 192];
    int n = blockIdx.z, ob = blockIdx.y * 16;
    int tx = threadIdx.x;
    for (int e = tx; e < 16 * Cc; e += 128) sW[e] = Wt[ob * Cc + e];
    __syncthreads();
    const float* Xn = X + (size_t)n * xStrideN;
    int pb = blockIdx.x * 512;
    float acc[16][4];
#pragma unroll
    for (int o = 0; o < 16; o++)
#pragma unroll
        for (int s = 0; s < 4; s++) acc[o][s] = 0.f;
    for (int c = 0; c < Cc; c++) {
        float xv[4];
#pragma unroll
        for (int s = 0; s < 4; s++) {
            int p = pb + s * 128 + tx;
            xv[s] = (p < P) ? Xn[(size_t)c * P + p] : 0.f;
        }
#pragma unroll
        for (int o = 0; o < 16; o++) {
            float w = sW[o * Cc + c];
#pragma unroll
            for (int s = 0; s < 4; s++) acc[o][s] += w * xv[s];
        }
    }
#pragma unroll
    for (int o = 0; o < 16; o++) {
        float b = Bs ? Bs[ob + o] : 0.f;
#pragma unroll
        for (int s = 0; s < 4; s++) {
            int p = pb + s * 128 + tx;
            if (p < P) Y[(size_t)n * yStrideN + (size_t)(ob + o) * P + p] = acc[o][s] + b;
        }
    }
}

// ---------------- complex GEMM kernels ----------------
// Y[b][i][j] = sum_k Xr[b][i][k] * M[j][k]   (real image x complex matrix^T)
__global__ void __launch_bounds__(256)
k_rxMT(const float* __restrict__ Xb, int cPerN, int cOff,
       const float2* __restrict__ M, float2* __restrict__ Y, int J) {
    __shared__ float  sA[32][33];
    __shared__ float2 sB[32][33];   // transposed: sB[k][j]
    int b = blockIdx.z;
    const float* X = Xb + (size_t)((b >> 4) * cPerN + cOff + (b & 15)) * PP;
    int j0 = blockIdx.x * 32, i0 = blockIdx.y * 32;
    int tx = threadIdx.x, ty = threadIdx.y, tid = ty * 32 + tx;
    float2 acc[4] = {{0,0},{0,0},{0,0},{0,0}};
    for (int kt = 0; kt < 128; kt += 32) {
#pragma unroll
        for (int s = 0; s < 4; s++) {
            int e = tid + s * 256; int r = e >> 5, c = e & 31;
            sA[r][c] = X[(i0 + r) * 128 + kt + c];
            float2 v = (j0 + r < J) ? M[(j0 + r) * 128 + kt + c] : make_float2(0.f, 0.f);
            sB[c][r] = v;
        }
        __syncthreads();
#pragma unroll
        for (int kk = 0; kk < 32; kk++) {
            float2 bv = sB[kk][tx];
#pragma unroll
            for (int ii = 0; ii < 4; ii++) {
                float a = sA[ty + 8 * ii][kk];
                acc[ii].x += a * bv.x; acc[ii].y += a * bv.y;
            }
        }
        __syncthreads();
    }
    if (j0 + tx < J) {
#pragma unroll
        for (int ii = 0; ii < 4; ii++)
            Y[((size_t)b * 128 + i0 + ty + 8 * ii) * J + j0 + tx] = acc[ii];
    }
}

// Y[b][i][j] = sum_k Xc[b][i][k] * M[j][k]   (complex x complex matrix^T)
__global__ void __launch_bounds__(256)
k_cMT(const float2* __restrict__ Xc, const float2* __restrict__ M,
      float2* __restrict__ Y, int J) {
    __shared__ float2 sA[32][33];
    __shared__ float2 sB[32][33];
    int b = blockIdx.z;
    const float2* X = Xc + (size_t)b * 128 * 128;
    int j0 = blockIdx.x * 32, i0 = blockIdx.y * 32;
    int tx = threadIdx.x, ty = threadIdx.y, tid = ty * 32 + tx;
    float2 acc[4] = {{0,0},{0,0},{0,0},{0,0}};
    for (int kt = 0; kt < 128; kt += 32) {
#pragma unroll
        for (int s = 0; s < 4; s++) {
            int e = tid + s * 256; int r = e >> 5, c = e & 31;
            sA[r][c] = X[(i0 + r) * 128 + kt + c];
            float2 v = (j0 + r < J) ? M[(j0 + r) * 128 + kt + c] : make_float2(0.f, 0.f);
            sB[c][r] = v;
        }
        __syncthreads();
#pragma unroll
        for (int kk = 0; kk < 32; kk++) {
            float2 bv = sB[kk][tx];
#pragma unroll
            for (int ii = 0; ii < 4; ii++) {
                float2 a = sA[ty + 8 * ii][kk];
                acc[ii].x += a.x * bv.x - a.y * bv.y;
                acc[ii].y += a.x * bv.y + a.y * bv.x;
            }
        }
        __syncthreads();
    }
    if (j0 + tx < J) {
#pragma unroll
        for (int ii = 0; ii < 4; ii++)
            Y[((size_t)b * 128 + i0 + ty + 8 * ii) * J + j0 + tx] = acc[ii];
    }
}

// Y[b][i][j] = sum_k M[i][k] * Xc[b][k][j]   (complex matrix x complex)
__global__ void __launch_bounds__(256)
k_MxX(const float2* __restrict__ M, const float2* __restrict__ Xc,
      float2* __restrict__ Y, int J) {
    __shared__ float2 sA[32][33];  // M[i][k]
    __shared__ float2 sB[32][33];  // X[k][j]
    int b = blockIdx.z;
    const float2* X = Xc + (size_t)b * 128 * J;
    int j0 = blockIdx.x * 32, i0 = blockIdx.y * 32;
    int tx = threadIdx.x, ty = threadIdx.y, tid = ty * 32 + tx;
    float2 acc[4] = {{0,0},{0,0},{0,0},{0,0}};
    for (int kt = 0; kt < 128; kt += 32) {
#pragma unroll
        for (int s = 0; s < 4; s++) {
            int e = tid + s * 256; int r = e >> 5, c = e & 31;
            sA[r][c] = M[(i0 + r) * 128 + kt + c];
            float2 v = (j0 + c < J) ? X[(size_t)(kt + r) * J + j0 + c] : make_float2(0.f, 0.f);
            sB[r][c] = v;
        }
        __syncthreads();
#pragma unroll
        for (int kk = 0; kk < 32; kk++) {
            float2 bv = sB[kk][tx];
#pragma unroll
            for (int ii = 0; ii < 4; ii++) {
                float2 a = sA[ty + 8 * ii][kk];
                acc[ii].x += a.x * bv.x - a.y * bv.y;
                acc[ii].y += a.x * bv.y + a.y * bv.x;
            }
        }
        __syncthreads();
    }
    if (j0 + tx < J) {
#pragma unroll
        for (int ii = 0; ii < 4; ii++)
            Y[((size_t)b * 128 + i0 + ty + 8 * ii) * J + j0 + tx] = acc[ii];
    }
}

// x_1o[b][h][w] = sum_k Re( T3[b][h][k] * Bw[k][w] ), write to cat ch 32..47
__global__ void k_irfft_w(const float2* __restrict__ T3, float* __restrict__ Ybase) {
    int b = blockIdx.z;
    int tx = threadIdx.x, ty = threadIdx.y;
    int hbase = blockIdx.y * 16;
    float acc[4] = {0.f, 0.f, 0.f, 0.f};
    for (int k = 0; k < JW; k++) {
        float2 bw = g_Bw[k * 128 + tx];
#pragma unroll
        for (int s = 0; s < 4; s++) {
            float2 a = T3[((size_t)b * 128 + hbase + ty * 4 + s) * JW + k];
            acc[s] += a.x * bw.x - a.y * bw.y;
        }
    }
    int n = b >> 4, c = b & 15;
    float* Y = Ybase + (size_t)(n * C1c + 32 + c) * PP;
#pragma unroll
    for (int s = 0; s < 4; s++)
        Y[(hbase + ty * 4 + s) * WW + tx] = acc[s];
}

// ---------------- 3x3 masked conv (mag * mask1 path) ----------------
__global__ void __launch_bounds__(256)
k_conv3(const float* __restrict__ X, const float* __restrict__ Wt,
        const float* __restrict__ Bs, float* __restrict__ Y) {
    __shared__ float sW[CMc * CMc * 9];
    __shared__ float sT[10][34];
    int tid = threadIdx.y * 32 + threadIdx.x;
    for (int e = tid; e < CMc * CMc * 9; e += 256) sW[e] = Wt[e];
    int n = blockIdx.z;
    int wb = blockIdx.x * 32, hb = blockIdx.y * 8;
    const float* Xn = X + (size_t)n * CMc * PP;
    float acc[CMc];
#pragma unroll
    for (int o = 0; o < CMc; o++) acc[o] = 0.f;
    for (int c = 0; c < CMc; c++) {
        __syncthreads();
        for (int e = tid; e < 340; e += 256) {
            int ly = e / 34, lx = e % 34;
            int gy = hb - 1 + ly, gx = wb - 1 + lx;
            float v = 0.f;
            if (gy >= 19 && gy < 109 && gx >= 19 && gx < 109)
                v = Xn[(size_t)c * PP + gy * WW + gx];
            sT[ly][lx] = v;
        }
        __syncthreads();
#pragma unroll
        for (int kh = 0; kh < 3; kh++)
#pragma unroll
            for (int kw = 0; kw < 3; kw++) {
                float xv = sT[threadIdx.y + kh][threadIdx.x + kw];
#pragma unroll
                for (int o = 0; o < CMc; o++)
                    acc[o] += sW[(o * CMc + c) * 9 + kh * 3 + kw] * xv;
            }
    }
    int h = hb + threadIdx.y, w = wb + threadIdx.x;
    bool in = (h >= 19 && h < 109 && w >= 19 && w < 109);
    float* Yn = Y + (size_t)n * CMc * PP;
#pragma unroll
    for (int o = 0; o < CMc; o++)
        Yn[(size_t)o * PP + h * WW + w] = in ? (acc[o] + Bs[o]) : 0.f;
}

// ---------------- elementwise ----------------
__global__ void k_magpha(const float2* __restrict__ Z, float* __restrict__ m,
                         float* __restrict__ p, int n) {
    int i = blockIdx.x * 256 + threadIdx.x;
    if (i >= n) return;
    float2 v = Z[i];
    m[i] = sqrtf(v.x * v.x + v.y * v.y);
    p[i] = atan2f(v.y, v.x);
}

__global__ void k_mm2(const float* __restrict__ mag, float* __restrict__ out) {
    int i = blockIdx.x * 256 + threadIdx.x;
    int h = (i >> 7) & 127, w = i & 127;
    bool in = (h >= 19 && h < 109 && w >= 19 && w < 109);
    out[i] = in ? 0.f : mag[i];
}

__global__ void k_combine(const float* __restrict__ A, const float* __restrict__ B,
                          float* __restrict__ S) {
    int i = blockIdx.x * 256 + threadIdx.x;
    int h = (i >> 7) & 127, w = i & 127;
    bool in = (h >= 19 && h < 109 && w >= 19 && w < 109);
    S[i] = in ? A[i] : B[i];
}

__global__ void k_makec(const float* __restrict__ m, const float* __restrict__ p,
                        float2* __restrict__ Z, int n) {
    int i = blockIdx.x * 256 + threadIdx.x;
    if (i >= n) return;
    float s, c;
    sincosf(p[i], &s, &c);
    float mv = m[i];
    Z[i] = make_float2(mv * c, mv * s);
}

__global__ void k_abscat(const float2* __restrict__ Z, float* __restrict__ cat) {
    int i = blockIdx.x * 256 + threadIdx.x;
    int b = i / PP, pp = i - b * PP;
    int n = b >> 4, c = b & 15;
    float2 v = Z[i];
    cat[(size_t)(n * C1c + 16 + c) * PP + pp] = sqrtf(v.x * v.x + v.y * v.y);
}

// ---------------- launch ----------------
extern "C" void kernel_launch(void* const* d_in, const int* in_sizes, int n_in,
                              void* d_out, int out_size) {
    const float* x        = (const float*)d_in[0];
    const float* conv1_w  = (const float*)d_in[1];
    const float* mag_s_w  = (const float*)d_in[2];
    const float* mag_s_b  = (const float*)d_in[3];
    const float* mag_f_w  = (const float*)d_in[4];
    const float* mag_f_b  = (const float*)d_in[5];
    const float* mag_w    = (const float*)d_in[6];
    const float* mag_b    = (const float*)d_in[7];
    const float* pha_w    = (const float*)d_in[8];
    const float* pha_b    = (const float*)d_in[9];
    const float* conv_0_w = (const float*)d_in[10];
    const float* conv_0_b = (const float*)d_in[11];
    const float* conv_1_w = (const float*)d_in[12];
    const float* conv_1_b = (const float*)d_in[13];
    const float* conv2_w  = (const float*)d_in[14];
    float* out = (float*)d_out;

    float  *px1, *pmag, *ppha, *pmm2, *pcA, *pcB, *pcS, *pmagout, *pphaout;
    float  *pfm, *pfp, *pmo, *ppo, *pcat;
    float2 *pM, *pMinv, *pFh, *pFhi, *pFw, *pT, *pF, *pT65, *pF65;
    cudaGetSymbolAddress((void**)&px1,    g_x1);
    cudaGetSymbolAddress((void**)&pmag,   g_mag);
    cudaGetSymbolAddress((void**)&ppha,   g_pha);
    cudaGetSymbolAddress((void**)&pmm2,   g_mm2);
    cudaGetSymbolAddress((void**)&pcA,    g_cA);
    cudaGetSymbolAddress((void**)&pcB,    g_cB);
    cudaGetSymbolAddress((void**)&pcS,    g_cS);
    cudaGetSymbolAddress((void**)&pmagout,g_magout);
    cudaGetSymbolAddress((void**)&pphaout,g_phaout);
    cudaGetSymbolAddress((void**)&pfm,    g_fm);
    cudaGetSymbolAddress((void**)&pfp,    g_fp);
    cudaGetSymbolAddress((void**)&pmo,    g_mo);
    cudaGetSymbolAddress((void**)&ppo,    g_po);
    cudaGetSymbolAddress((void**)&pcat,   g_cat);
    cudaGetSymbolAddress((void**)&pM,     g_M);
    cudaGetSymbolAddress((void**)&pMinv,  g_Minv);
    cudaGetSymbolAddress((void**)&pFh,    g_Fh);
    cudaGetSymbolAddress((void**)&pFhi,   g_Fhi);
    cudaGetSymbolAddress((void**)&pFw,    g_Fw);
    cudaGetSymbolAddress((void**)&pT,     g_T);
    cudaGetSymbolAddress((void**)&pF,     g_F);
    cudaGetSymbolAddress((void**)&pT65,   g_T65);
    cudaGetSymbolAddress((void**)&pF65,   g_F65);

    // matrices
    k_tables<<<1, 512>>>();
    k_dft<<<64, 256>>>();
    k_buildM<<<64, 256>>>();
    k_buildMinv<<<64, 256>>>();

    dim3 cb(32, 8);

    // conv1: 192 -> 48
    k_g1x1<<<dim3(32, 3, NB), 128>>>(x, conv1_w, nullptr, px1, 192, PP, 192 * PP, 48 * PP);

    // ---- FRFT forward: Fre = M @ X @ M^T  (x_05 = channels 16..31) ----
    k_rxMT<<<dim3(4, 4, BATCH), cb>>>(px1, C1c, 16, pM, pT, 128);
    k_MxX <<<dim3(4, 4, BATCH), cb>>>(pM, pT, pF, 128);
    k_magpha<<<4096, 256>>>(pF, pmag, ppha, BATCH * PP);

    // mag path
    k_mm2<<<4096, 256>>>(pmag, pmm2);
    k_conv3<<<dim3(4, 16, NB), cb>>>(pmag, mag_s_w, mag_s_b, pcA);
    k_g1x1<<<dim3(32, 1, NB), 128>>>(pmm2, mag_f_w, mag_f_b, pcB, 16, PP, 16 * PP, 16 * PP);
    k_combine<<<4096, 256>>>(pcA, pcB, pcS);
    k_g1x1<<<dim3(32, 1, NB), 128>>>(pcS, mag_w, mag_b, pmagout, 16, PP, 16 * PP, 16 * PP);
    k_g1x1<<<dim3(32, 1, NB), 128>>>(ppha, pha_w, pha_b, pphaout, 16, PP, 16 * PP, 16 * PP);
    k_makec<<<4096, 256>>>(pmagout, pphaout, pF, BATCH * PP);

    // ---- FRFT inverse: R = Minv @ FreOut @ Minv^T ; ifrft = |R| ----
    k_cMT<<<dim3(4, 4, BATCH), cb>>>(pF, pMinv, pT, 128);
    k_MxX<<<dim3(4, 4, BATCH), cb>>>(pMinv, pT, pF, 128);
    k_abscat<<<4096, 256>>>(pF, pcat);

    // ---- rfft2 branch (x_1 = channels 32..47) ----
    k_rxMT<<<dim3(3, 4, BATCH), cb>>>(px1, C1c, 32, pFw, pT65, JW);
    k_MxX <<<dim3(3, 4, BATCH), cb>>>(pFh, pT65, pF65, JW);
    k_magpha<<<(BATCH * P65 + 255) / 256, 256>>>(pF65, pfm, pfp, BATCH * P65);
    k_g1x1<<<dim3(17, 1, NB), 128>>>(pfm, conv_1_w, conv_1_b, pmo, 16, P65, 16 * P65, 16 * P65);
    k_g1x1<<<dim3(17, 1, NB), 128>>>(pfp, conv_1_w, conv_1_b, ppo, 16, P65, 16 * P65, 16 * P65);
    k_makec<<<(BATCH * P65 + 255) / 256, 256>>>(pmo, ppo, pF65, BATCH * P65);
    k_MxX<<<dim3(3, 4, BATCH), cb>>>(pFhi, pF65, pT65, JW);
    k_irfft_w<<<dim3(1, 8, BATCH), dim3(128, 4)>>>(pT65, pcat);

    // ---- x_0 branch into cat channels 0..15 ----
    k_g1x1<<<dim3(32, 1, NB), 128>>>(px1, conv_0_w, conv_0_b, pcat, 16, PP, 48 * PP, 48 * PP);

    // ---- conv2: 48 -> 192 ----
    k_g1x1<<<dim3(32, 12, NB), 128>>>(pcat, conv2_w, nullptr, out, 48, PP, 48 * PP, 192 * PP);
}

// round 6
// speedup vs baseline: 1.2153x; 1.2153x over previous
#include <cuda_runtime.h>
#include <math.h>

#define NB   4
#define CIN  192
#define HH   128
#define WW   128
#define PP   (HH*WW)       // 16384
#define C1c  48
#define C0c  16
#define CMc  16
#define BATCH 64           // NB * CMc
#define JW   65
#define P65  (128*JW)      // 8320

// ---------------- device scratch (no allocation allowed) ----------------
static __device__ float2 gf_chrp1[255];
static __device__ float2 gf_E[509];
static __device__ float  gf_S[509];
static __device__ float2 gf_fac[128];   // amp * exp(-i pi/8) * chrp2[r]

static __device__ float2  g_M   [128*128];
static __device__ float2  g_Cm  [128*128];
static __device__ float2  g_Minv[128*128];
static __device__ float2  g_Fh  [128*128];
static __device__ float2  g_Fhi [128*128];
static __device__ float2  g_Fw  [JW*128];
static __device__ float2  g_Bw  [JW*128];

static __device__ float   g_x1 [NB*C1c*PP];
static __device__ float2  g_T  [BATCH*128*128];
static __device__ float2  g_F  [BATCH*128*128];
static __device__ float   g_mag[BATCH*PP];
static __device__ float   g_pha[BATCH*PP];
static __device__ float   g_mm2[BATCH*PP];
static __device__ float   g_cA [BATCH*PP];
static __device__ float   g_cB [BATCH*PP];
static __device__ float   g_cS [BATCH*PP];
static __device__ float   g_magout[BATCH*PP];
static __device__ float   g_phaout[BATCH*PP];
static __device__ float2  g_T65[BATCH*P65];
static __device__ float2  g_F65[BATCH*P65];
static __device__ float   g_fm[BATCH*P65];
static __device__ float   g_fp[BATCH*P65];
static __device__ float   g_mo[BATCH*P65];
static __device__ float   g_po[BATCH*P65];
static __device__ float   g_cat[NB*C1c*PP];

// ---------------- table construction (tiny, fp64 for phase accuracy) -----
__global__ void k_tables() {
    int t = threadIdx.x;
    const double PI = 3.14159265358979323846;
    double tana2 = tan(PI / 8.0);     // tan(alpha/2), alpha = pi/4
    double sina  = sin(PI / 4.0);
    double coef  = tana2 / 512.0;     // chirp: exp(-i*pi*coef*n^2)
    double ec    = 1.0 / (512.0 * sina); // E: exp(+i*pi*ec*d^2)
    for (int j = t; j < 255; j += 512) {
        double n = (double)(j - 127);
        double s, c; sincospi(-coef * n * n, &s, &c);
        gf_chrp1[j] = make_float2((float)c, (float)s);
    }
    double amp = sqrt(1.0 / (512.0 * sina));
    double ps, pc; sincospi(-0.125, &ps, &pc);   // exp(-i pi/8)
    for (int r = t; r < 128; r += 512) {
        double n = 2.0 * r - 127.0;
        double s, c; sincospi(-coef * n * n, &s, &c);
        // f = amp * (pc + i ps) * (c + i s)
        gf_fac[r] = make_float2((float)(amp * (pc * c - ps * s)),
                                (float)(amp * (pc * s + ps * c)));
    }
    for (int i = t; i < 509; i += 512) {
        double d = (double)(i - 254);
        double s, c; sincospi(ec * d * d, &s, &c);
        gf_E[i] = make_float2((float)c, (float)s);
        int m = i - 254;
        double sv;
        if (m == 0) sv = 1.0;
        else if ((m & 1) == 0) sv = 0.0;
        else {
            double x = 0.5 * (double)m;
            sv = sinpi(x) / (PI * x);
        }
        gf_S[i] = (float)sv;
    }
}

__global__ void k_dft() {
    int idx = blockIdx.x * 256 + threadIdx.x;
    if (idx < 128 * 128) {
        int u = idx >> 7, v = idx & 127;
        int e1 = ((u + 64) * (v + 64)) & 127;
        double s, c; sincospi(2.0 * e1 / 128.0, &s, &c);
        double inv = 1.0 / sqrt(128.0);
        g_Cm[idx] = make_float2((float)(c * inv), (float)(s * inv));
        int e2 = (u * v) & 127;
        double s2, c2; sincospi(-2.0 * e2 / 128.0, &s2, &c2);
        g_Fh[idx] = make_float2((float)c2, (float)s2);
        double s3, c3; sincospi(2.0 * e2 / 128.0, &s3, &c3);
        g_Fhi[idx] = make_float2((float)(c3 / 128.0), (float)(s3 / 128.0));
    }
    if (idx < JW * 128) {
        int k = idx / 128, w = idx & 127;
        int e = (k * w) & 127;
        double s, c; sincospi(-2.0 * e / 128.0, &s, &c);
        g_Fw[idx] = make_float2((float)c, (float)s);
        float2 bw;
        if (k == 0)       bw = make_float2(1.0f / 128.0f, 0.f);
        else if (k == 64) bw = make_float2(((w & 1) ? -1.0f : 1.0f) / 128.0f, 0.f);
        else {
            double s4, c4; sincospi(2.0 * e / 128.0, &s4, &c4);
            bw = make_float2((float)(c4 * 2.0 / 128.0), (float)(s4 * 2.0 / 128.0));
        }
        g_Bw[idx] = bw;
    }
}

// fp32 accumulation: ~128 nonzero terms of O(1) magnitude -> ~1e-6 rel err
__global__ void k_buildM() {
    int idx = blockIdx.x * 256 + threadIdx.x;
    if (idx >= 128 * 128) return;
    int r = idx >> 7, k = idx & 127;
    float ax = 0.f, ay = 0.f;
    // m = j - 2k: nonzero S only for odd m or m==0 (j == 2k)
    {   // m == 0 term: S = 1
        int j = 2 * k;
        float2 c1 = gf_chrp1[j];
        float2 e  = gf_E[2 * r - j + 254];
        ax += c1.x * e.x - c1.y * e.y;
        ay += c1.x * e.y + c1.y * e.x;
    }
    for (int j = 1; j < 255; j += 2) {   // odd j -> odd m
        float s = gf_S[j - 2 * k + 254];
        float2 c1 = gf_chrp1[j];
        float2 e  = gf_E[2 * r - j + 254];
        ax += (c1.x * e.x - c1.y * e.y) * s;
        ay += (c1.x * e.y + c1.y * e.x) * s;
    }
    float2 f = gf_fac[r];
    g_M[idx] = make_float2(f.x * ax - f.y * ay, f.x * ay + f.y * ax);
}

__global__ void k_buildMinv() {
    int idx = blockIdx.x * 256 + threadIdx.x;
    if (idx >= 128 * 128) return;
    int r = idx >> 7, v = idx & 127;
    float ax = 0.f, ay = 0.f;
#pragma unroll 8
    for (int u = 0; u < 128; u++) {
        float2 a = g_M[r * 128 + u];
        float2 b = g_Cm[u * 128 + v];
        ax += a.x * b.x - a.y * b.y;
        ay += a.x * b.y + a.y * b.x;
    }
    g_Minv[idx] = make_float2(ax, ay);
}

// ---------------- generic 1x1 conv (GEMM) ----------------
__global__ void __launch_bounds__(128)
k_g1x1(const float* __restrict__ X, const float* __restrict__ Wt,
       const float* __restrict__ Bs, float* __restrict__ Y,
       int Cc, int P, int xStrideN, int yStrideN) {
    __shared__ float sW[16 * 192];
    int n = blockIdx.z, ob = blockIdx.y * 16;
    int tx = threadIdx.x;
    for (int e = tx; e < 16 * Cc; e += 128) sW[e] = Wt[ob * Cc + e];
    __syncthreads();
    const float* Xn = X + (size_t)n * xStrideN;
    int pb = blockIdx.x * 512;
    float acc[16][4];
#pragma unroll
    for (int o = 0; o < 16; o++)
#pragma unroll
        for (int s = 0; s < 4; s++) acc[o][s] = 0.f;
    for (int c = 0; c < Cc; c++) {
        float xv[4];
#pragma unroll
        for (int s = 0; s < 4; s++) {
            int p = pb + s * 128 + tx;
            xv[s] = (p < P) ? Xn[(size_t)c * P + p] : 0.f;
        }
#pragma unroll
        for (int o = 0; o < 16; o++) {
            float w = sW[o * Cc + c];
#pragma unroll
            for (int s = 0; s < 4; s++) acc[o][s] += w * xv[s];
        }
    }
#pragma unroll
    for (int o = 0; o < 16; o++) {
        float b = Bs ? Bs[ob + o] : 0.f;
#pragma unroll
        for (int s = 0; s < 4; s++) {
            int p = pb + s * 128 + tx;
            if (p < P) Y[(size_t)n * yStrideN + (size_t)(ob + o) * P + p] = acc[o][s] + b;
        }
    }
}

// ---------------- 64x64-tile complex GEMMs (16x16 thr, 4x4 micro) --------
// Y[b][i][j] = sum_k X[b-real][i][k] * M[j][k]
__global__ void __launch_bounds__(256)
k_rxMT64(const float* __restrict__ Xb, int cPerN, int cOff,
         const float2* __restrict__ M, float2* __restrict__ Y, int J) {
    __shared__ float  sA[64][17];
    __shared__ float2 sB[16][65];
    int b = blockIdx.z;
    const float* X = Xb + (size_t)((b >> 4) * cPerN + cOff + (b & 15)) * PP;
    int j0 = blockIdx.x * 64, i0 = blockIdx.y * 64;
    int tid = threadIdx.x;
    int tx = tid & 15, ty = tid >> 4;
    float2 acc[4][4];
#pragma unroll
    for (int a = 0; a < 4; a++)
#pragma unroll
        for (int c = 0; c < 4; c++) acc[a][c] = make_float2(0.f, 0.f);
    for (int kt = 0; kt < 128; kt += 16) {
#pragma unroll
        for (int s = 0; s < 4; s++) {
            int e = tid + s * 256; int r = e >> 4, c = e & 15;
            sA[r][c] = X[(i0 + r) * 128 + kt + c];
            float2 v = (j0 + r < J) ? M[(j0 + r) * 128 + kt + c] : make_float2(0.f, 0.f);
            sB[c][r] = v;
        }
        __syncthreads();
#pragma unroll
        for (int kk = 0; kk < 16; kk++) {
            float av[4]; float2 bv[4];
#pragma unroll
            for (int ii = 0; ii < 4; ii++) av[ii] = sA[ty * 4 + ii][kk];
#pragma unroll
            for (int jj = 0; jj < 4; jj++) bv[jj] = sB[kk][tx * 4 + jj];
#pragma unroll
            for (int ii = 0; ii < 4; ii++)
#pragma unroll
                for (int jj = 0; jj < 4; jj++) {
                    acc[ii][jj].x += av[ii] * bv[jj].x;
                    acc[ii][jj].y += av[ii] * bv[jj].y;
                }
        }
        __syncthreads();
    }
#pragma unroll
    for (int ii = 0; ii < 4; ii++)
#pragma unroll
        for (int jj = 0; jj < 4; jj++) {
            int j = j0 + tx * 4 + jj;
            if (j < J)
                Y[((size_t)b * 128 + i0 + ty * 4 + ii) * J + j] = acc[ii][jj];
        }
}

// Y[b][i][j] = sum_k Xc[b][i][k] * M[j][k]
__global__ void __launch_bounds__(256)
k_cMT64(const float2* __restrict__ Xc, const float2* __restrict__ M,
        float2* __restrict__ Y, int J) {
    __shared__ float2 sA[64][17];
    __shared__ float2 sB[16][65];
    int b = blockIdx.z;
    const float2* X = Xc + (size_t)b * 128 * 128;
    int j0 = blockIdx.x * 64, i0 = blockIdx.y * 64;
    int tid = threadIdx.x;
    int tx = tid & 15, ty = tid >> 4;
    float2 acc[4][4];
#pragma unroll
    for (int a = 0; a < 4; a++)
#pragma unroll
        for (int c = 0; c < 4; c++) acc[a][c] = make_float2(0.f, 0.f);
    for (int kt = 0; kt < 128; kt += 16) {
#pragma unroll
        for (int s = 0; s < 4; s++) {
            int e = tid + s * 256; int r = e >> 4, c = e & 15;
            sA[r][c] = X[(i0 + r) * 128 + kt + c];
            float2 v = (j0 + r < J) ? M[(j0 + r) * 128 + kt + c] : make_float2(0.f, 0.f);
            sB[c][r] = v;
        }
        __syncthreads();
#pragma unroll
        for (int kk = 0; kk < 16; kk++) {
            float2 av[4]; float2 bv[4];
#pragma unroll
            for (int ii = 0; ii < 4; ii++) av[ii] = sA[ty * 4 + ii][kk];
#pragma unroll
            for (int jj = 0; jj < 4; jj++) bv[jj] = sB[kk][tx * 4 + jj];
#pragma unroll
            for (int ii = 0; ii < 4; ii++)
#pragma unroll
                for (int jj = 0; jj < 4; jj++) {
                    acc[ii][jj].x += av[ii].x * bv[jj].x - av[ii].y * bv[jj].y;
                    acc[ii][jj].y += av[ii].x * bv[jj].y + av[ii].y * bv[jj].x;
                }
        }
        __syncthreads();
    }
#pragma unroll
    for (int ii = 0; ii < 4; ii++)
#pragma unroll
        for (int jj = 0; jj < 4; jj++) {
            int j = j0 + tx * 4 + jj;
            if (j < J)
                Y[((size_t)b * 128 + i0 + ty * 4 + ii) * J + j] = acc[ii][jj];
        }
}

// Y[b][i][j] = sum_k M[i][k] * Xc[b][k][j] with templated epilogue:
// MODE 0: write complex Y
// MODE 1: write o1=mag, o2=pha, (o3=mm2 masked mag if non-null)
// MODE 2: write |.| into cat (channels 16..31)
template <int MODE>
__global__ void __launch_bounds__(256)
k_MxX64(const float2* __restrict__ M, const float2* __restrict__ Xc,
        float2* __restrict__ Y, float* __restrict__ o1, float* __restrict__ o2,
        float* __restrict__ o3, int J) {
    __shared__ float2 sA[64][17];
    __shared__ float2 sB[16][65];
    int b = blockIdx.z;
    const float2* X = Xc + (size_t)b * 128 * J;
    int j0 = blockIdx.x * 64, i0 = blockIdx.y * 64;
    int tid = threadIdx.x;
    int tx = tid & 15, ty = tid >> 4;
    float2 acc[4][4];
#pragma unroll
    for (int a = 0; a < 4; a++)
#pragma unroll
        for (int c = 0; c < 4; c++) acc[a][c] = make_float2(0.f, 0.f);
    for (int kt = 0; kt < 128; kt += 16) {
#pragma unroll
        for (int s = 0; s < 4; s++) {
            int e = tid + s * 256;
            int r = e >> 4, c = e & 15;
            sA[r][c] = M[(i0 + r) * 128 + kt + c];
            int r2 = e >> 6, c2 = e & 63;
            float2 v = (j0 + c2 < J) ? X[(size_t)(kt + r2) * J + j0 + c2]
                                     : make_float2(0.f, 0.f);
            sB[r2][c2] = v;
        }
        __syncthreads();
#pragma unroll
        for (int kk = 0; kk < 16; kk++) {
            float2 av[4]; float2 bv[4];
#pragma unroll
            for (int ii = 0; ii < 4; ii++) av[ii] = sA[ty * 4 + ii][kk];
#pragma unroll
            for (int jj = 0; jj < 4; jj++) bv[jj] = sB[kk][tx * 4 + jj];
#pragma unroll
            for (int ii = 0; ii < 4; ii++)
#pragma unroll
                for (int jj = 0; jj < 4; jj++) {
                    acc[ii][jj].x += av[ii].x * bv[jj].x - av[ii].y * bv[jj].y;
                    acc[ii][jj].y += av[ii].x * bv[jj].y + av[ii].y * bv[jj].x;
                }
        }
        __syncthreads();
    }
#pragma unroll
    for (int ii = 0; ii < 4; ii++)
#pragma unroll
        for (int jj = 0; jj < 4; jj++) {
            int i = i0 + ty * 4 + ii;
            int j = j0 + tx * 4 + jj;
            if (j >= J) continue;
            float2 v = acc[ii][jj];
            if (MODE == 0) {
                Y[((size_t)b * 128 + i) * J + j] = v;
            } else if (MODE == 1) {
                size_t idx = ((size_t)b * 128 + i) * J + j;
                float m = sqrtf(v.x * v.x + v.y * v.y);
                o1[idx] = m;
                o2[idx] = atan2f(v.y, v.x);
                if (o3) {
                    bool in = (i >= 19 && i < 109 && j >= 19 && j < 109);
                    o3[idx] = in ? 0.f : m;
                }
            } else {
                int n = b >> 4, c = b & 15;
                o1[(size_t)(n * C1c + 16 + c) * PP + i * 128 + j] =
                    sqrtf(v.x * v.x + v.y * v.y);
            }
        }
}

// x_1o[b][h][w] = sum_k Re( T3[b][h][k] * Bw[k][w] ), write to cat ch 32..47
__global__ void k_irfft_w(const float2* __restrict__ T3, float* __restrict__ Ybase) {
    int b = blockIdx.z;
    int tx = threadIdx.x, ty = threadIdx.y;
    int hbase = blockIdx.y * 16;
    float acc[4] = {0.f, 0.f, 0.f, 0.f};
    for (int k = 0; k < JW; k++) {
        float2 bw = g_Bw[k * 128 + tx];
#pragma unroll
        for (int s = 0; s < 4; s++) {
            float2 a = T3[((size_t)b * 128 + hbase + ty * 4 + s) * JW + k];
            acc[s] += a.x * bw.x - a.y * bw.y;
        }
    }
    int n = b >> 4, c = b & 15;
    float* Yp = Ybase + (size_t)(n * C1c + 32 + c) * PP;
#pragma unroll
    for (int s = 0; s < 4; s++)
        Yp[(hbase + ty * 4 + s) * WW + tx] = acc[s];
}

// ---------------- 3x3 masked conv (mag * mask1 path) ----------------
__global__ void __launch_bounds__(256)
k_conv3(const float* __restrict__ X, const float* __restrict__ Wt,
        const float* __restrict__ Bs, float* __restrict__ Y) {
    __shared__ float sW[CMc * CMc * 9];
    __shared__ float sT[10][34];
    int tid = threadIdx.y * 32 + threadIdx.x;
    for (int e = tid; e < CMc * CMc * 9; e += 256) sW[e] = Wt[e];
    int n = blockIdx.z;
    int wb = blockIdx.x * 32, hb = blockIdx.y * 8;
    const float* Xn = X + (size_t)n * CMc * PP;
    float acc[CMc];
#pragma unroll
    for (int o = 0; o < CMc; o++) acc[o] = 0.f;
    for (int c = 0; c < CMc; c++) {
        __syncthreads();
        for (int e = tid; e < 340; e += 256) {
            int ly = e / 34, lx = e % 34;
            int gy = hb - 1 + ly, gx = wb - 1 + lx;
            float v = 0.f;
            if (gy >= 19 && gy < 109 && gx >= 19 && gx < 109)
                v = Xn[(size_t)c * PP + gy * WW + gx];
            sT[ly][lx] = v;
        }
        __syncthreads();
#pragma unroll
        for (int kh = 0; kh < 3; kh++)
#pragma unroll
            for (int kw = 0; kw < 3; kw++) {
                float xv = sT[threadIdx.y + kh][threadIdx.x + kw];
#pragma unroll
                for (int o = 0; o < CMc; o++)
                    acc[o] += sW[(o * CMc + c) * 9 + kh * 3 + kw] * xv;
            }
    }
    int h = hb + threadIdx.y, w = wb + threadIdx.x;
    bool in = (h >= 19 && h < 109 && w >= 19 && w < 109);
    float* Yn = Y + (size_t)n * CMc * PP;
#pragma unroll
    for (int o = 0; o < CMc; o++)
        Yn[(size_t)o * PP + h * WW + w] = in ? (acc[o] + Bs[o]) : 0.f;
}

// ---------------- elementwise ----------------
__global__ void k_combine(const float* __restrict__ A, const float* __restrict__ B,
                          float* __restrict__ S) {
    int i = blockIdx.x * 256 + threadIdx.x;
    int h = (i >> 7) & 127, w = i & 127;
    bool in = (h >= 19 && h < 109 && w >= 19 && w < 109);
    S[i] = in ? A[i] : B[i];
}

__global__ void k_makec(const float* __restrict__ m, const float* __restrict__ p,
                        float2* __restrict__ Z, int n) {
    int i = blockIdx.x * 256 + threadIdx.x;
    if (i >= n) return;
    float s, c;
    sincosf(p[i], &s, &c);
    float mv = m[i];
    Z[i] = make_float2(mv * c, mv * s);
}

// ---------------- launch ----------------
extern "C" void kernel_launch(void* const* d_in, const int* in_sizes, int n_in,
                              void* d_out, int out_size) {
    const float* x        = (const float*)d_in[0];
    const float* conv1_w  = (const float*)d_in[1];
    const float* mag_s_w  = (const float*)d_in[2];
    const float* mag_s_b  = (const float*)d_in[3];
    const float* mag_f_w  = (const float*)d_in[4];
    const float* mag_f_b  = (const float*)d_in[5];
    const float* mag_w    = (const float*)d_in[6];
    const float* mag_b    = (const float*)d_in[7];
    const float* pha_w    = (const float*)d_in[8];
    const float* pha_b    = (const float*)d_in[9];
    const float* conv_0_w = (const float*)d_in[10];
    const float* conv_0_b = (const float*)d_in[11];
    const float* conv_1_w = (const float*)d_in[12];
    const float* conv_1_b = (const float*)d_in[13];
    const float* conv2_w  = (const float*)d_in[14];
    float* out = (float*)d_out;

    float  *px1, *pmag, *ppha, *pmm2, *pcA, *pcB, *pcS, *pmagout, *pphaout;
    float  *pfm, *pfp, *pmo, *ppo, *pcat;
    float2 *pM, *pMinv, *pFh, *pFhi, *pFw, *pT, *pF, *pT65, *pF65;
    cudaGetSymbolAddress((void**)&px1,    g_x1);
    cudaGetSymbolAddress((void**)&pmag,   g_mag);
    cudaGetSymbolAddress((void**)&ppha,   g_pha);
    cudaGetSymbolAddress((void**)&pmm2,   g_mm2);
    cudaGetSymbolAddress((void**)&pcA,    g_cA);
    cudaGetSymbolAddress((void**)&pcB,    g_cB);
    cudaGetSymbolAddress((void**)&pcS,    g_cS);
    cudaGetSymbolAddress((void**)&pmagout,g_magout);
    cudaGetSymbolAddress((void**)&pphaout,g_phaout);
    cudaGetSymbolAddress((void**)&pfm,    g_fm);
    cudaGetSymbolAddress((void**)&pfp,    g_fp);
    cudaGetSymbolAddress((void**)&pmo,    g_mo);
    cudaGetSymbolAddress((void**)&ppo,    g_po);
    cudaGetSymbolAddress((void**)&pcat,   g_cat);
    cudaGetSymbolAddress((void**)&pM,     g_M);
    cudaGetSymbolAddress((void**)&pMinv,  g_Minv);
    cudaGetSymbolAddress((void**)&pFh,    g_Fh);
    cudaGetSymbolAddress((void**)&pFhi,   g_Fhi);
    cudaGetSymbolAddress((void**)&pFw,    g_Fw);
    cudaGetSymbolAddress((void**)&pT,     g_T);
    cudaGetSymbolAddress((void**)&pF,     g_F);
    cudaGetSymbolAddress((void**)&pT65,   g_T65);
    cudaGetSymbolAddress((void**)&pF65,   g_F65);

    // constant matrices (all fp32 accumulation now)
    k_tables<<<1, 512>>>();
    k_dft<<<64, 256>>>();
    k_buildM<<<64, 256>>>();
    k_buildMinv<<<64, 256>>>();

    // conv1: 192 -> 48
    k_g1x1<<<dim3(32, 3, NB), 128>>>(x, conv1_w, nullptr, px1, 192, PP, 192 * PP, 48 * PP);

    // ---- FRFT forward: Fre = M @ X @ M^T  (x_05 = channels 16..31) ----
    k_rxMT64<<<dim3(2, 2, BATCH), 256>>>(px1, C1c, 16, pM, pT, 128);
    k_MxX64<1><<<dim3(2, 2, BATCH), 256>>>(pM, pT, nullptr, pmag, ppha, pmm2, 128);

    // mag path
    k_conv3<<<dim3(4, 16, NB), dim3(32, 8)>>>(pmag, mag_s_w, mag_s_b, pcA);
    k_g1x1<<<dim3(32, 1, NB), 128>>>(pmm2, mag_f_w, mag_f_b, pcB, 16, PP, 16 * PP, 16 * PP);
    k_combine<<<4096, 256>>>(pcA, pcB, pcS);
    k_g1x1<<<dim3(32, 1, NB), 128>>>(pcS, mag_w, mag_b, pmagout, 16, PP, 16 * PP, 16 * PP);
    k_g1x1<<<dim3(32, 1, NB), 128>>>(ppha, pha_w, pha_b, pphaout, 16, PP, 16 * PP, 16 * PP);
    k_makec<<<4096, 256>>>(pmagout, pphaout, pF, BATCH * PP);

    // ---- FRFT inverse: R = Minv @ FreOut @ Minv^T ; ifrft = |R| -> cat ----
    k_cMT64<<<dim3(2, 2, BATCH), 256>>>(pF, pMinv, pT, 128);
    k_MxX64<2><<<dim3(2, 2, BATCH), 256>>>(pMinv, pT, nullptr, pcat, nullptr, nullptr, 128);

    // ---- rfft2 branch (x_1 = channels 32..47) ----
    k_rxMT64<<<dim3(2, 2, BATCH), 256>>>(px1, C1c, 32, pFw, pT65, JW);
    k_MxX64<1><<<dim3(2, 2, BATCH), 256>>>(pFh, pT65, nullptr, pfm, pfp, nullptr, JW);
    k_g1x1<<<dim3(17, 1, NB), 128>>>(pfm, conv_1_w, conv_1_b, pmo, 16, P65, 16 * P65, 16 * P65);
    k_g1x1<<<dim3(17, 1, NB), 128>>>(pfp, conv_1_w, conv_1_b, ppo, 16, P65, 16 * P65, 16 * P65);
    k_makec<<<(BATCH * P65 + 255) / 256, 256>>>(pmo, ppo, pF65, BATCH * P65);
    k_MxX64<0><<<dim3(2, 2, BATCH), 256>>>(pFhi, pF65, pT65, nullptr, nullptr, nullptr, JW);
    k_irfft_w<<<dim3(1, 8, BATCH), dim3(128, 4)>>>(pT65, pcat);

    // ---- x_0 branch into cat channels 0..15 ----
    k_g1x1<<<dim3(32, 1, NB), 128>>>(px1, conv_0_w, conv_0_b, pcat, 16, PP, 48 * PP, 48 * PP);

    // ---- conv2: 48 -> 192 ----
    k_g1x1<<<dim3(32, 12, NB), 128>>>(pcat, conv2_w, nullptr, out, 48, PP, 48 * PP, 192 * PP);
}